// round 17
// baseline (speedup 1.0000x reference)
#include <cuda_runtime.h>
#include <cuda_fp16.h>
#include <math.h>
#include <stdint.h>

// Problem constants
#define NN    8192
#define DEG   16
#define FIN   1024
#define FOUT  128
#define NH    8

// GEMM config: CTA 64x128 (one head), 4 warps, warp tile 32x64
#define BM 64
#define BN 128
#define BK 32
#define NCH (FIN / BK)    // 32
#define NSTAGE 4
#define AS_STRIDE 40
#define BS_STRIDE 136
#define A_BYTES (BM * AS_STRIDE * 2)           // 5120
#define B_BYTES (BK * BS_STRIDE * 2)           // 8704
#define STAGE_BYTES (A_BYTES + B_BYTES)        // 13824
#define RED_OFF  (NSTAGE * STAGE_BYTES)        // 55296
#define BIAS_OFF (RED_OFF + 1024)              // 56320
#define SMEM_BYTES (BIAS_OFF + 1536)           // 57856

#define GEMM_CTAS_PER_HEAD (NN / BM)           // 128
#define GEMM_CTAS (GEMM_CTAS_PER_HEAD * NH)    // 1024
#define ATTN_NODES_PER_CTA 8                   // 4 warps x 2 nodes
#define ATTN_CTAS_PER_HEAD (NN / ATTN_NODES_PER_CTA)   // 1024
#define TOTAL_CTAS (GEMM_CTAS + ATTN_CTAS_PER_HEAD * NH) // 9216

// ---------------------------------------------------------------------------
// Scratch (device globals — no allocs allowed)
// ---------------------------------------------------------------------------
__device__ __half g_hh[(size_t)NH * NN * FOUT];   // 16 MB
__device__ float g_sd[NH * NN];
__device__ float g_ss[NH * NN];
__device__ __half g_Xh[(size_t)NN * FIN];         // 16 MB
__device__ __half g_Wh[(size_t)NH * FIN * FOUT];  // 2 MB
__device__ int   g_done[NH];                      // per-head GEMM completion

// ---------------------------------------------------------------------------
// helpers
// ---------------------------------------------------------------------------
__device__ __forceinline__ uint32_t smem_u32(const void* p) {
    uint32_t a;
    asm("{ .reg .u64 t; cvta.to.shared.u64 t, %1; cvt.u32.u64 %0, t; }" : "=r"(a) : "l"(p));
    return a;
}
__device__ __forceinline__ void cpasync16(uint32_t dst, const void* src) {
    asm volatile("cp.async.cg.shared.global [%0], [%1], 16;"
                 :: "r"(dst), "l"(__cvta_generic_to_global(src)) : "memory");
}
__device__ __forceinline__ void ldsm_x4(uint32_t* r, uint32_t addr) {
    asm volatile("ldmatrix.sync.aligned.m8n8.x4.shared.b16 {%0,%1,%2,%3}, [%4];"
                 : "=r"(r[0]), "=r"(r[1]), "=r"(r[2]), "=r"(r[3]) : "r"(addr));
}
__device__ __forceinline__ void ldsm_x4_t(uint32_t* r, uint32_t addr) {
    asm volatile("ldmatrix.sync.aligned.m8n8.x4.trans.shared.b16 {%0,%1,%2,%3}, [%4];"
                 : "=r"(r[0]), "=r"(r[1]), "=r"(r[2]), "=r"(r[3]) : "r"(addr));
}
__device__ __forceinline__ void mma_f16(float* d, const uint32_t* a, const uint32_t* b) {
    asm volatile(
        "mma.sync.aligned.m16n8k16.row.col.f32.f16.f16.f32 "
        "{%0,%1,%2,%3}, {%4,%5,%6,%7}, {%8,%9}, {%0,%1,%2,%3};"
        : "+f"(d[0]), "+f"(d[1]), "+f"(d[2]), "+f"(d[3])
        : "r"(a[0]), "r"(a[1]), "r"(a[2]), "r"(a[3]), "r"(b[0]), "r"(b[1]));
}

// ---------------------------------------------------------------------------
// Prep: X -> fp16, W -> fp16; also re-zero the dependency counters.
// ---------------------------------------------------------------------------
#define XBLK (NN * FIN / 4 / 512)                 // 4096
#define WBLK (NH * FIN * FOUT / 4 / 512)          // 512
__global__ __launch_bounds__(256) void conv_xw(
    const float* __restrict__ X, const float* __restrict__ W)
{
    int b = blockIdx.x;
    if (b == 0 && threadIdx.x < NH) g_done[threadIdx.x] = 0;
    const float4* src;
    __half* dst;
    size_t base;
    if (b < XBLK) {
        base = (size_t)b * 512 + threadIdx.x;
        src = (const float4*)X;
        dst = g_Xh;
    } else {
        base = (size_t)(b - XBLK) * 512 + threadIdx.x;
        src = (const float4*)W;
        dst = g_Wh;
    }
    float4 v0 = src[base];
    float4 v1 = src[base + 256];
    __half h0[4] = { __float2half_rn(v0.x), __float2half_rn(v0.y),
                     __float2half_rn(v0.z), __float2half_rn(v0.w) };
    __half h1[4] = { __float2half_rn(v1.x), __float2half_rn(v1.y),
                     __float2half_rn(v1.z), __float2half_rn(v1.w) };
    *(uint2*)(dst + base * 4)         = *(uint2*)h0;
    *(uint2*)(dst + (base + 256) * 4) = *(uint2*)h1;
}

// ---------------------------------------------------------------------------
// Megakernel: CTAs [0, 1024) = GEMM tiles (head-major); after each head's 128
// tiles complete they release that head's attn CTAs. CTAs [1024, 9216) = attn
// (head-major, 8 nodes per CTA), spin-waiting on g_done[head].
// 128 threads everywhere.
// ---------------------------------------------------------------------------
__global__ __launch_bounds__(128, 3) void gat_mega(
    const float* __restrict__ bW, const float* __restrict__ av,
    const int* __restrict__ adj, const float* __restrict__ ba,
    float* __restrict__ out)
{
    extern __shared__ char smem[];
    const int tid = threadIdx.x, wid = tid >> 5, lane = tid & 31;

    if (blockIdx.x < GEMM_CTAS) {
        // ================= GEMM branch =================
        const uint32_t sb = smem_u32(smem);
        float* sRed  = (float*)(smem + RED_OFF);
        float* sBias = (float*)(smem + BIAS_OFF);
        float* sAd   = sBias + 128;
        float* sAs   = sAd + 128;

        const int hd = blockIdx.x >> 7;               // head-major
        const int m0 = (blockIdx.x & 127) * BM;
        const int mw = (wid & 1) * 32;
        const int nh = wid >> 1;
        const int nw = nh * 64;

        sBias[tid] = bW[hd * FOUT + tid];
        sAd[tid]   = av[hd * 2 * FOUT + tid];
        sAs[tid]   = av[hd * 2 * FOUT + FOUT + tid];

        float acc[2][8][4];
#pragma unroll
        for (int a = 0; a < 2; a++)
#pragma unroll
            for (int b = 0; b < 8; b++)
#pragma unroll
                for (int c = 0; c < 4; c++) acc[a][b][c] = 0.f;

        const int a_row = tid >> 2, a_col = (tid & 3) * 8;
        const int b_row = tid >> 4, b_col = (tid & 15) * 8;

        auto issue_loads = [&](int i) {
            const int kk = i * BK;
            const uint32_t as = sb + (i % NSTAGE) * STAGE_BYTES;
            const uint32_t bs = as + A_BYTES;
#pragma unroll
            for (int p = 0; p < 2; p++) {
                int row = a_row + p * 32;
                cpasync16(as + (row * AS_STRIDE + a_col) * 2,
                          g_Xh + (size_t)(m0 + row) * FIN + kk + a_col);
            }
#pragma unroll
            for (int p = 0; p < 4; p++) {
                int row = b_row + p * 8;
                cpasync16(bs + (row * BS_STRIDE + b_col) * 2,
                          g_Wh + ((size_t)hd * FIN + kk + row) * FOUT + b_col);
            }
            asm volatile("cp.async.commit_group;" ::: "memory");
        };

        issue_loads(0);
        issue_loads(1);
        issue_loads(2);

        const int lr = lane & 15, lh = (lane >> 4) << 3;

        for (int i = 0; i < NCH; i++) {
            asm volatile("cp.async.wait_group 2;" ::: "memory");
            __syncthreads();
            if (i + 3 < NCH) issue_loads(i + 3);
            else asm volatile("cp.async.commit_group;" ::: "memory");

            const uint32_t as = sb + (i % NSTAGE) * STAGE_BYTES;
            const uint32_t bs = as + A_BYTES;

#pragma unroll
            for (int ks = 0; ks < 2; ks++) {
                const int k16 = ks * 16;
                uint32_t afr[2][4], bfr[4][4];
#pragma unroll
                for (int mt = 0; mt < 2; mt++)
                    ldsm_x4(afr[mt], as + ((mw + mt * 16 + lr) * AS_STRIDE + k16 + lh) * 2);
#pragma unroll
                for (int nt2 = 0; nt2 < 4; nt2++)
                    ldsm_x4_t(bfr[nt2], bs + ((k16 + lr) * BS_STRIDE + nw + nt2 * 16 + lh) * 2);
#pragma unroll
                for (int mt = 0; mt < 2; mt++)
#pragma unroll
                    for (int nt = 0; nt < 8; nt++)
                        mma_f16(acc[mt][nt], afr[mt], &bfr[nt >> 1][(nt & 1) * 2]);
            }
        }

        // ---- epilogue ----
        const int lq = lane >> 2, qt = lane & 3;
#pragma unroll
        for (int mt = 0; mt < 2; mt++) {
#pragma unroll
            for (int s = 0; s < 2; s++) {
                const int row = mw + mt * 16 + lq + s * 8;
                __half* dst = g_hh + ((size_t)hd * NN + m0 + row) * FOUT;
                float pd = 0.f, ps = 0.f;
#pragma unroll
                for (int nt = 0; nt < 8; nt++) {
                    int col = nw + nt * 8 + qt * 2;
                    float t0 = acc[mt][nt][2 * s + 0] + sBias[col];
                    float t1 = acc[mt][nt][2 * s + 1] + sBias[col + 1];
                    pd += t0 * sAd[col] + t1 * sAd[col + 1];
                    ps += t0 * sAs[col] + t1 * sAs[col + 1];
                    *(__half2*)(dst + col) = __floats2half2_rn(t0, t1);
                }
                pd += __shfl_xor_sync(0xffffffffu, pd, 1);
                pd += __shfl_xor_sync(0xffffffffu, pd, 2);
                ps += __shfl_xor_sync(0xffffffffu, ps, 1);
                ps += __shfl_xor_sync(0xffffffffu, ps, 2);
                if (qt == 0) {
                    sRed[(nh * 64 + row) * 2 + 0] = pd;
                    sRed[(nh * 64 + row) * 2 + 1] = ps;
                }
            }
        }
        __syncthreads();
        if (tid < 64) {
            const int row = tid;
            g_sd[hd * NN + m0 + row] = sRed[row * 2 + 0] + sRed[(64 + row) * 2 + 0];
            g_ss[hd * NN + m0 + row] = sRed[row * 2 + 1] + sRed[(64 + row) * 2 + 1];
        }
        __syncthreads();
        if (tid == 0) {
            __threadfence();
            atomicAdd(&g_done[hd], 1);
        }
    } else {
        // ================= attention branch =================
        const int bid2 = blockIdx.x - GEMM_CTAS;
        const int hd   = bid2 >> 10;                      // head-major
        const int nb   = (bid2 & 1023) * ATTN_NODES_PER_CTA;

        // wait for this head's GEMM tiles
        if (tid == 0) {
            while (atomicAdd(&g_done[hd], 0) < GEMM_CTAS_PER_HEAD)
                __nanosleep(200);
        }
        __syncthreads();
        __threadfence();

        const int half = lane >> 4, li = lane & 15;
        const int n = nb + wid * 2 + half;                // warp = 2 nodes

        const __half* Hh = g_hh + (size_t)hd * NN * FOUT;
        const int nbr = adj[n * DEG + li];

        const float sdst = g_sd[hd * NN + n];
        const float bah  = ba[hd];

        float s = sdst + g_ss[hd * NN + nbr] + bah;
        float score = (s > 0.f) ? s : 0.2f * s;
        float s2 = sdst + g_ss[hd * NN + n] + bah;
        float sself = (s2 > 0.f) ? s2 : 0.2f * s2;

        float mx = score;
#pragma unroll
        for (int off = 8; off; off >>= 1)
            mx = fmaxf(mx, __shfl_xor_sync(0xffffffffu, mx, off));
        mx = fmaxf(mx, sself);
        float e = __expf(score - mx);
        float eself = __expf(sself - mx);
        float sum = e;
#pragma unroll
        for (int off = 8; off; off >>= 1)
            sum += __shfl_xor_sync(0xffffffffu, sum, off);
        sum += eself;
        const float inv = 1.0f / sum;
        const float alpha = e * inv;
        const float aself = eself * inv;

        float a8[8] = {0.f, 0.f, 0.f, 0.f, 0.f, 0.f, 0.f, 0.f};
        const size_t coff = (size_t)li * 8;
#pragma unroll
        for (int d = 0; d < DEG; d++) {
            const int src = half * 16 + d;
            float ad = __shfl_sync(0xffffffffu, alpha, src);
            int idx  = __shfl_sync(0xffffffffu, nbr, src);
            uint4 v = *(const uint4*)(Hh + (size_t)idx * FOUT + coff);
            float2 f0 = __half22float2(*(__half2*)&v.x);
            float2 f1 = __half22float2(*(__half2*)&v.y);
            float2 f2 = __half22float2(*(__half2*)&v.z);
            float2 f3 = __half22float2(*(__half2*)&v.w);
            a8[0] += ad * f0.x; a8[1] += ad * f0.y;
            a8[2] += ad * f1.x; a8[3] += ad * f1.y;
            a8[4] += ad * f2.x; a8[5] += ad * f2.y;
            a8[6] += ad * f3.x; a8[7] += ad * f3.y;
        }
        {   // self row
            uint4 v = *(const uint4*)(Hh + (size_t)n * FOUT + coff);
            float2 f0 = __half22float2(*(__half2*)&v.x);
            float2 f1 = __half22float2(*(__half2*)&v.y);
            float2 f2 = __half22float2(*(__half2*)&v.z);
            float2 f3 = __half22float2(*(__half2*)&v.w);
            a8[0] += aself * f0.x; a8[1] += aself * f0.y;
            a8[2] += aself * f1.x; a8[3] += aself * f1.y;
            a8[4] += aself * f2.x; a8[5] += aself * f2.y;
            a8[6] += aself * f3.x; a8[7] += aself * f3.y;
        }

        float* dst = out + (size_t)n * (NH * FOUT) + hd * FOUT + li * 8;
        *(float4*)(dst + 0) = make_float4(a8[0], a8[1], a8[2], a8[3]);
        *(float4*)(dst + 4) = make_float4(a8[4], a8[5], a8[6], a8[7]);
    }
}

// ---------------------------------------------------------------------------
extern "C" void kernel_launch(void* const* d_in, const int* in_sizes, int n_in,
                              void* d_out, int out_size)
{
    const float* X   = (const float*)d_in[0];
    const int*   adj = (const int*)  d_in[1];
    const float* W   = (const float*)d_in[2];
    const float* bW  = (const float*)d_in[3];
    const float* av  = (const float*)d_in[4];
    const float* ba  = (const float*)d_in[5];
    float* out = (float*)d_out;

    cudaFuncSetAttribute(gat_mega,
                         cudaFuncAttributeMaxDynamicSharedMemorySize, SMEM_BYTES);

    conv_xw<<<XBLK + WBLK, 256>>>(X, W);
    gat_mega<<<TOTAL_CTAS, 128, SMEM_BYTES>>>(bW, av, adj, ba, out);
}